// round 15
// baseline (speedup 1.0000x reference)
#include <cuda_runtime.h>
#include <cuda_fp16.h>
#include <cstdint>

#define CIN     32
#define COUT    32
#define KVOL    27
#define WARPS   18
#define THREADS 576
#define ROWS_W  32
#define W_TAP   2048
#define WBYTES  (KVOL * W_TAP)          // 55296
#define OFF_BIAS WBYTES
#define OFF_IDX (WBYTES + 128)          // 55424
#define NSLOT   8
#define SLOTB   256                     // 128B idx + 128B valid
#define SMEM_TOTAL (OFF_IDX + WARPS * NSLOT * SLOTB)   // 92288
#define CAP     1000000

// K-permuted fp16 feature table (64 MB device scratch)
__device__ __align__(16) __half g_feath[(size_t)CAP * 32];
__device__ int g_valid_is_u8;

__device__ __forceinline__ uint32_t smem_u32(const void* p) {
    uint32_t a;
    asm("{ .reg .u64 t; cvta.to.shared.u64 t, %1; cvt.u32.u64 %0, t; }" : "=r"(a) : "l"(p));
    return a;
}
__device__ __forceinline__ void cp16(uint32_t dst, const void* src, uint32_t nbytes) {
    asm volatile("cp.async.cg.shared.global [%0], [%1], 16, %2;"
                 :: "r"(dst), "l"(src), "r"(nbytes) : "memory");
}
#define CP_COMMIT() asm volatile("cp.async.commit_group;" ::: "memory")
#define CP_WAIT3()  asm volatile("cp.async.wait_group 3;" ::: "memory")

__device__ __forceinline__ uint32_t h2pack(float a, float b) {
    __half2 h = __floats2half2_rn(a, b);
    return *(uint32_t*)&h;
}
__device__ __forceinline__ void mma_f16(float& d0, float& d1, float& d2, float& d3,
                                        uint32_t a0, uint32_t a1, uint32_t a2, uint32_t a3,
                                        uint32_t b0, uint32_t b1) {
    asm volatile(
        "mma.sync.aligned.m16n8k16.row.col.f32.f16.f16.f32 "
        "{%0,%1,%2,%3}, {%4,%5,%6,%7}, {%8,%9}, {%0,%1,%2,%3};"
        : "+f"(d0), "+f"(d1), "+f"(d2), "+f"(d3)
        : "r"(a0), "r"(a1), "r"(a2), "r"(a3), "r"(b0), "r"(b1));
}
// predicated 16B global load: zero if n==0
__device__ __forceinline__ uint4 ldg_cond(const void* p, uint32_t n) {
    uint4 v;
    asm volatile(
        "{\n\t.reg .pred p;\n\t"
        "setp.ne.u32 p, %5, 0;\n\t"
        "mov.v4.u32 {%0,%1,%2,%3}, {0,0,0,0};\n\t"
        "@p ld.global.nc.v4.u32 {%0,%1,%2,%3}, [%4];\n\t}"
        : "=r"(v.x), "=r"(v.y), "=r"(v.z), "=r"(v.w)
        : "l"(p), "r"(n));
    return v;
}

// prepass: permuted fp16 table (validated) + valid-dtype detection
__global__ void prepass(const float* __restrict__ feat,
                        const unsigned char* __restrict__ kvalid, int N) {
    if (blockIdx.x == 0 && threadIdx.x < 32) {
        int nz = 0;
        for (int i = threadIdx.x; i < 4096; i += 32)
            if ((i & 3) && kvalid[i]) nz = 1;
        nz = __any_sync(0xffffffffu, nz);
        if (threadIdx.x == 0) g_valid_is_u8 = nz;
    }
    int stride = gridDim.x * blockDim.x;
    int total = N * 8;
    for (int i = blockIdx.x * blockDim.x + threadIdx.x; i < total; i += stride) {
        int n = i >> 3, s = i & 7;
        int tig = s >> 1, kc = s & 1;
        const float* src = feat + (size_t)n * 32 + kc * 16 + 2 * tig;
        uint2 o;
        o.x = h2pack(src[0], src[1]);
        o.y = h2pack(src[8], src[9]);
        ((uint2*)g_feath)[(size_t)n * 8 + tig * 2 + kc] = o;
    }
}

// ---------------- main kernel ----------------
__global__ void __launch_bounds__(THREADS, 1)
spconv_mma(const float* __restrict__ weight,
           const float* __restrict__ bias,
           const int* __restrict__ kidx,
           const unsigned char* __restrict__ kvalid,
           float* __restrict__ out,
           int N)
{
    extern __shared__ __align__(16) char smem[];
    const uint32_t sb = smem_u32(smem);

    const int tid  = threadIdx.x;
    const int w    = tid >> 5;
    const int lane = tid & 31;
    const int gid  = lane >> 2;
    const int tig  = lane & 3;
    const bool u8  = (g_valid_is_u8 != 0);
    const int* kvalid32 = (const int*)kvalid;

    // pack fp16 B fragments (validated layout)
    for (int i = tid; i < KVOL * 512; i += THREADS) {
        int tap = i >> 9, d = i & 511;
        int p = d >> 7, ln = (d >> 2) & 31, q = d & 3;
        int kc = p >> 1;
        int nt = (p & 1) * 2 + (q >> 1);
        int tg = ln & 3, gd = ln >> 2;
        int k = kc * 16 + 2 * tg + ((q & 1) ? 8 : 0);
        const float* wrow = weight + (size_t)tap * 1024;
        ((uint32_t*)smem)[(size_t)tap * 512 + d] =
            h2pack(wrow[k * 32 + nt * 8 + gd], wrow[(k + 1) * 32 + nt * 8 + gd]);
    }
    if (tid < 32) ((float*)(smem + OFF_BIAS))[tid] = bias[tid];
    __syncthreads();

    const int ntiles = (N + ROWS_W - 1) / ROWS_W;
    const int TW     = gridDim.x * WARPS;
    const int gw     = blockIdx.x * WARPS + w;

    int myT = 0;
    for (int t = gw; t < ntiles; t += TW) myT++;
    const int total = myT * KVOL;
    if (total == 0) return;

    const uint32_t ixBase = sb + OFF_IDX + (uint32_t)w * (NSLOT * SLOTB);
    const char*    idxsm  = smem + OFF_IDX + (size_t)w * (NSLOT * SLOTB);
    const char*    fbl    = (const char*)g_feath + (tig << 4);   // per-lane hoisted base

    // idx-prefetch cursor (monotone over jobs); prologue starts at job 2
    int iTap = 2;
    int iOff = 2 * N + gw * ROWS_W;
    const int wrapAdj = TW * ROWS_W - (KVOL - 1) * N;

    auto idx_cp = [&](int slot) {
        uint32_t db = ixBase + (uint32_t)slot * SLOTB;
        if (lane < 8) {
            cp16(db + lane * 16, (const char*)kidx + (((size_t)iOff + lane * 4) << 2), 16u);
        } else if (lane < 16) {
            int l = lane - 8;
            if (u8) {
                if (l < 2) cp16(db + 128 + l * 16, (const char*)kvalid + (size_t)iOff + l * 16, 16u);
            } else {
                cp16(db + 128 + l * 16, (const char*)kvalid + (((size_t)iOff + l * 4) << 2), 16u);
            }
        }
        if (++iTap == KVOL) { iTap = 0; iOff += wrapAdj; }
        else iOff += N;
    };
    auto lds_idx = [&](int slot, int* iv, uint32_t* nv) {
        const char* p = idxsm + (size_t)slot * SLOTB;
        #pragma unroll
        for (int q = 0; q < 4; q++) {
            iv[q] = ((const int*)p)[gid + 8 * q];
            bool va = u8 ? (((const unsigned char*)(p + 128))[gid + 8 * q] != 0)
                         : (((const int*)(p + 128))[gid + 8 * q] != 0);
            nv[q] = va ? 16u : 0u;
        }
    };

    // ---- prologue: A for jobs 0 (X) and 1 (Y) via sync idx; idx slots for jobs 2..5 ----
    uint4 X[4], Y[4];
    {
        #pragma unroll
        for (int job = 0; job < 2; job++) {
            uint4* B = job ? Y : X;
            #pragma unroll
            for (int q = 0; q < 4; q++) {
                int o = job * N + gw * ROWS_W + gid + 8 * q;
                int id = kidx[o];
                bool va = u8 ? (kvalid[o] != 0) : (kvalid32[o] != 0);
                B[q] = ldg_cond(fbl + ((size_t)(uint32_t)id << 6), va ? 16u : 0u);
            }
        }
        #pragma unroll
        for (int s = 2; s <= 5; s++) {   // slots (= jobs) 2..5
            idx_cp(s & (NSLOT - 1));
            CP_COMMIT();
        }
    }

    int ctap = 0;
    int cRow = gw * ROWS_W;

    float acc[2][4][4];
    #pragma unroll
    for (int s = 0; s < 2; s++)
        #pragma unroll
        for (int nt = 0; nt < 4; nt++)
            #pragma unroll
            for (int r = 0; r < 4; r++) acc[s][nt][r] = 0.0f;

    auto body = [&](int jl, uint4* A) {
        CP_WAIT3();
        __syncwarp();

        // idx for job jl+2 (slot written 4+ groups ago — guaranteed complete)
        int iv[4]; uint32_t nv[4];
        const bool ld2 = (jl + 2 < total);
        if (ld2) lds_idx((jl + 2) & (NSLOT - 1), iv, nv);

        // B fragments for this tap
        const uint4* wp = (const uint4*)(smem + (size_t)ctap * W_TAP);
        uint4 bf0 = wp[0 * 32 + lane];
        uint4 bf1 = wp[1 * 32 + lane];
        uint4 bf2 = wp[2 * 32 + lane];
        uint4 bf3 = wp[3 * 32 + lane];

        // compute both subtiles from A (validated block)
        #pragma unroll
        for (int s = 0; s < 2; s++) {
            uint4 L = A[2 * s];
            uint4 M = A[2 * s + 1];
            mma_f16(acc[s][0][0], acc[s][0][1], acc[s][0][2], acc[s][0][3],
                    L.x, M.x, L.y, M.y, bf0.x, bf0.y);
            mma_f16(acc[s][1][0], acc[s][1][1], acc[s][1][2], acc[s][1][3],
                    L.x, M.x, L.y, M.y, bf0.z, bf0.w);
            mma_f16(acc[s][2][0], acc[s][2][1], acc[s][2][2], acc[s][2][3],
                    L.x, M.x, L.y, M.y, bf1.x, bf1.y);
            mma_f16(acc[s][3][0], acc[s][3][1], acc[s][3][2], acc[s][3][3],
                    L.x, M.x, L.y, M.y, bf1.z, bf1.w);
            mma_f16(acc[s][0][0], acc[s][0][1], acc[s][0][2], acc[s][0][3],
                    L.z, M.z, L.w, M.w, bf2.x, bf2.y);
            mma_f16(acc[s][1][0], acc[s][1][1], acc[s][1][2], acc[s][1][3],
                    L.z, M.z, L.w, M.w, bf2.z, bf2.w);
            mma_f16(acc[s][2][0], acc[s][2][1], acc[s][2][2], acc[s][2][3],
                    L.z, M.z, L.w, M.w, bf3.x, bf3.y);
            mma_f16(acc[s][3][0], acc[s][3][1], acc[s][3][2], acc[s][3][3],
                    L.z, M.z, L.w, M.w, bf3.z, bf3.w);
        }

        // refill this parity's buffer with A for job jl+2 (2-job lead)
        if (ld2) {
            #pragma unroll
            for (int q = 0; q < 4; q++)
                A[q] = ldg_cond(fbl + ((size_t)(uint32_t)iv[q] << 6), nv[q]);
        }
        // idx prefetch for job jl+6
        if (jl + 6 < total) idx_cp((jl + 6) & (NSLOT - 1));
        CP_COMMIT();

        if (++ctap == KVOL) {
            const float* bsm = (const float*)(smem + OFF_BIAS);
            #pragma unroll
            for (int s = 0; s < 2; s++) {
                int gr = cRow + s * 16 + gid;
                #pragma unroll
                for (int nt = 0; nt < 4; nt++) {
                    int col = nt * 8 + tig * 2;
                    float2 bv = *(const float2*)(bsm + col);
                    if (gr < N) {
                        float2 o = { acc[s][nt][0] + bv.x, acc[s][nt][1] + bv.y };
                        *(float2*)(out + (size_t)gr * COUT + col) = o;
                    }
                    if (gr + 8 < N) {
                        float2 o = { acc[s][nt][2] + bv.x, acc[s][nt][3] + bv.y };
                        *(float2*)(out + (size_t)(gr + 8) * COUT + col) = o;
                    }
                    acc[s][nt][0] = acc[s][nt][1] = acc[s][nt][2] = acc[s][nt][3] = 0.0f;
                }
            }
            ctap = 0;
            cRow += TW * ROWS_W;
        }
    };

    int jl = 0;
    while (jl + 2 <= total) {
        body(jl, X);
        body(jl + 1, Y);
        jl += 2;
    }
    if (jl < total) body(jl, X);
}

extern "C" void kernel_launch(void* const* d_in, const int* in_sizes, int n_in,
                              void* d_out, int out_size) {
    const float*         feat   = (const float*)d_in[0];          // [N, 32]
    const float*         weight = (const float*)d_in[1];          // [27, 32, 32]
    const float*         bias   = (const float*)d_in[2];          // [32]
    const int*           kidx   = (const int*)d_in[3];            // [27, N]
    const unsigned char* kvalid = (const unsigned char*)d_in[4];  // [27, N] bool
    float* out = (float*)d_out;

    const int N = in_sizes[0] / CIN;

    int sms = 148;
    cudaDeviceGetAttribute(&sms, cudaDevAttrMultiProcessorCount, 0);

    cudaFuncSetAttribute(spconv_mma, cudaFuncAttributeMaxDynamicSharedMemorySize, SMEM_TOTAL);

    prepass<<<sms * 8, 256>>>(feat, kvalid, N);
    spconv_mma<<<sms, THREADS, SMEM_TOTAL>>>(weight, bias, kidx, kvalid, out, N);
}

// round 16
// speedup vs baseline: 2.0867x; 2.0867x over previous
#include <cuda_runtime.h>
#include <cuda_fp16.h>
#include <cstdint>

#define CIN     32
#define COUT    32
#define KVOL    27
#define WARPS   24
#define THREADS 768
#define NSTAGE  3
#define ROWS_W  32
#define SLICE   2048                    // 32 rows * 64 B
#define W_TAP   2048
#define WBYTES  (KVOL * W_TAP)          // 55296
#define OFF_BIAS WBYTES
#define OFF_A   (WBYTES + 128)          // 55424
#define OFF_IDX (OFF_A + WARPS * NSTAGE * SLICE)       // 202880
#define NSLOT   4
#define SLOTB   256                     // 128B idx + 128B valid
#define SMEM_TOTAL (OFF_IDX + WARPS * NSLOT * SLOTB)   // 227456
#define CAP     1000000

// K-permuted fp16 feature table (64 MB device scratch)
__device__ __align__(16) __half g_feath[(size_t)CAP * 32];
__device__ int g_valid_is_u8;

__device__ __forceinline__ uint32_t smem_u32(const void* p) {
    uint32_t a;
    asm("{ .reg .u64 t; cvta.to.shared.u64 t, %1; cvt.u32.u64 %0, t; }" : "=r"(a) : "l"(p));
    return a;
}
__device__ __forceinline__ void cp16(uint32_t dst, const void* src, uint32_t nbytes) {
    asm volatile("cp.async.cg.shared.global [%0], [%1], 16, %2;"
                 :: "r"(dst), "l"(src), "r"(nbytes) : "memory");
}
// fully predicated: NO instruction effect when pred==0 (stale smem left behind)
__device__ __forceinline__ void cp16p(uint32_t dst, const void* src, uint32_t pred) {
    asm volatile(
        "{\n\t.reg .pred p;\n\t"
        "setp.ne.u32 p, %2, 0;\n\t"
        "@p cp.async.cg.shared.global [%0], [%1], 16;\n\t}"
        :: "r"(dst), "l"(src), "r"(pred) : "memory");
}
#define CP_COMMIT() asm volatile("cp.async.commit_group;" ::: "memory")
#define CP_WAIT2()  asm volatile("cp.async.wait_group 2;" ::: "memory")

__device__ __forceinline__ uint32_t h2pack(float a, float b) {
    __half2 h = __floats2half2_rn(a, b);
    return *(uint32_t*)&h;
}
__device__ __forceinline__ void mma_f16(float& d0, float& d1, float& d2, float& d3,
                                        uint32_t a0, uint32_t a1, uint32_t a2, uint32_t a3,
                                        uint32_t b0, uint32_t b1) {
    asm volatile(
        "mma.sync.aligned.m16n8k16.row.col.f32.f16.f16.f32 "
        "{%0,%1,%2,%3}, {%4,%5,%6,%7}, {%8,%9}, {%0,%1,%2,%3};"
        : "+f"(d0), "+f"(d1), "+f"(d2), "+f"(d3)
        : "r"(a0), "r"(a1), "r"(a2), "r"(a3), "r"(b0), "r"(b1));
}
__device__ __forceinline__ void mask4(uint4& v, uint32_t m) {
    v.x &= m; v.y &= m; v.z &= m; v.w &= m;
}

// prepass: permuted fp16 table (validated) + valid-dtype detection
__global__ void prepass(const float* __restrict__ feat,
                        const unsigned char* __restrict__ kvalid, int N) {
    if (blockIdx.x == 0 && threadIdx.x < 32) {
        int nz = 0;
        for (int i = threadIdx.x; i < 4096; i += 32)
            if ((i & 3) && kvalid[i]) nz = 1;
        nz = __any_sync(0xffffffffu, nz);
        if (threadIdx.x == 0) g_valid_is_u8 = nz;
    }
    int stride = gridDim.x * blockDim.x;
    int total = N * 8;
    for (int i = blockIdx.x * blockDim.x + threadIdx.x; i < total; i += stride) {
        int n = i >> 3, s = i & 7;
        int tig = s >> 1, kc = s & 1;
        const float* src = feat + (size_t)n * 32 + kc * 16 + 2 * tig;
        uint2 o;
        o.x = h2pack(src[0], src[1]);
        o.y = h2pack(src[8], src[9]);
        ((uint2*)g_feath)[(size_t)n * 8 + tig * 2 + kc] = o;
    }
}

// ---------------- main kernel ----------------
__global__ void __launch_bounds__(THREADS, 1)
spconv_mma(const float* __restrict__ weight,
           const float* __restrict__ bias,
           const int* __restrict__ kidx,
           const unsigned char* __restrict__ kvalid,
           float* __restrict__ out,
           int N)
{
    extern __shared__ __align__(16) char smem[];
    const uint32_t sb = smem_u32(smem);

    const int tid  = threadIdx.x;
    const int w    = tid >> 5;
    const int lane = tid & 31;
    const int gid  = lane >> 2;
    const int tig  = lane & 3;
    const bool u8  = (g_valid_is_u8 != 0);
    const int* kvalid32 = (const int*)kvalid;

    // pack fp16 B fragments (validated layout)
    for (int i = tid; i < KVOL * 512; i += THREADS) {
        int tap = i >> 9, d = i & 511;
        int p = d >> 7, ln = (d >> 2) & 31, q = d & 3;
        int kc = p >> 1;
        int nt = (p & 1) * 2 + (q >> 1);
        int tg = ln & 3, gd = ln >> 2;
        int k = kc * 16 + 2 * tg + ((q & 1) ? 8 : 0);
        const float* wrow = weight + (size_t)tap * 1024;
        ((uint32_t*)smem)[(size_t)tap * 512 + d] =
            h2pack(wrow[k * 32 + nt * 8 + gd], wrow[(k + 1) * 32 + nt * 8 + gd]);
    }
    if (tid < 32) ((float*)(smem + OFF_BIAS))[tid] = bias[tid];
    __syncthreads();

    const int ntiles = (N + ROWS_W - 1) / ROWS_W;
    const int TW     = gridDim.x * WARPS;
    const int gw     = blockIdx.x * WARPS + w;

    int myT = 0;
    for (int t = gw; t < ntiles; t += TW) myT++;
    const int total = myT * KVOL;
    if (total == 0) return;

    const uint32_t aBase  = sb + OFF_A + (uint32_t)(w * NSTAGE) * SLICE;
    const uint32_t ixBase = sb + OFF_IDX + (uint32_t)w * (NSLOT * SLOTB);
    const char*    idxsm  = smem + OFF_IDX + (size_t)w * (NSLOT * SLOTB);
    const char*    fbase  = (const char*)g_feath;
    const uint32_t dst0   = (uint32_t)gid * 64 + (uint32_t)tig * 16;  // lane-private

    // idx-prefetch cursor (monotone over jobs); prologue issues jobs 2,3
    int iTap = 2;
    int iOff = 2 * N + gw * ROWS_W;
    const int wrapAdj = TW * ROWS_W - (KVOL - 1) * N;

    auto idx_cp = [&](int slot) {
        uint32_t db = ixBase + (uint32_t)slot * SLOTB;
        if (lane < 8) {
            cp16(db + lane * 16, (const char*)kidx + (((size_t)iOff + lane * 4) << 2), 16u);
        } else if (lane < 16) {
            int l = lane - 8;
            if (u8) {
                if (l < 2) cp16(db + 128 + l * 16, (const char*)kvalid + (size_t)iOff + l * 16, 16u);
            } else {
                cp16(db + 128 + l * 16, (const char*)kvalid + (((size_t)iOff + l * 4) << 2), 16u);
            }
        }
        if (++iTap == KVOL) { iTap = 0; iOff += wrapAdj; }
        else iOff += N;
    };
    // idx + validity nibble for this lane's 4 rows (gid+8q)
    auto lds_idx = [&](int slot, int* iv) -> uint32_t {
        const char* p = idxsm + (size_t)slot * SLOTB;
        uint32_t m = 0;
        #pragma unroll
        for (int q = 0; q < 4; q++) {
            iv[q] = ((const int*)p)[gid + 8 * q];
            bool va = u8 ? (((const unsigned char*)(p + 128))[gid + 8 * q] != 0)
                         : (((const int*)(p + 128))[gid + 8 * q] != 0);
            m |= va ? (1u << q) : 0u;
        }
        return m;
    };
    // predicated gather: only valid rows issue LDGSTS
    auto gatherp = [&](const int* iv, uint32_t m, int stage) {
        uint32_t ab = aBase + (uint32_t)stage * SLICE + dst0;
        #pragma unroll
        for (int q = 0; q < 4; q++)
            cp16p(ab + q * 512u, fbase + ((size_t)(uint32_t)iv[q] << 6) + (tig << 4),
                  (m >> q) & 1u);
    };

    // ---- prologue: gather jobs 0,1; idx slots for jobs 2,3 (group order = steady state) ----
    uint32_t vsr = 0;                    // validity nibbles: [0]=job jl, [1]=jl+1, [2]=jl+2
    {
        int iv[4];
        #pragma unroll
        for (int job = 0; job < 2; job++) {
            uint32_t m = 0;
            #pragma unroll
            for (int q = 0; q < 4; q++) {
                int o = job * N + gw * ROWS_W + gid + 8 * q;
                iv[q] = kidx[o];
                bool va = u8 ? (kvalid[o] != 0) : (kvalid32[o] != 0);
                m |= va ? (1u << q) : 0u;
            }
            vsr |= m << (4 * job);
            gatherp(iv, m, job);
            CP_COMMIT();                 // G: gather(job)
            idx_cp(2 + job);
            CP_COMMIT();                 // G: idx(job+2)
        }
    }

    int pstage = 2, cstage = 0;
    int ctap = 0;
    int cRow = gw * ROWS_W;

    float acc[2][4][4];
    #pragma unroll
    for (int s = 0; s < 2; s++)
        #pragma unroll
        for (int nt = 0; nt < 4; nt++)
            #pragma unroll
            for (int r = 0; r < 4; r++) acc[s][nt][r] = 0.0f;

    for (int jl = 0; jl < total; jl++) {
        // wait: all but 2 newest groups complete => gather(jl) + idx(jl+2) done
        CP_WAIT2();
        __syncwarp();

        // issue gather for job jl+2 (idx slot guaranteed complete)
        if (jl + 2 < total) {
            int iv[4];
            uint32_t m = lds_idx((jl + 2) & (NSLOT - 1), iv);
            vsr |= m << 8;
            gatherp(iv, m, pstage);
            if (++pstage == NSTAGE) pstage = 0;
        }
        CP_COMMIT();
        // idx prefetch for job jl+4
        if (jl + 4 < total) idx_cp((jl + 4) & (NSLOT - 1));
        CP_COMMIT();

        const char* Ab = (const char*)smem + OFF_A
                       + (size_t)(w * NSTAGE + cstage) * SLICE;
        if (++cstage == NSTAGE) cstage = 0;

        // A fragments (lane-private bytes) + validity masking of stale smem
        uint4 A0 = *(const uint4*)(Ab + dst0);
        uint4 A1 = *(const uint4*)(Ab + dst0 + 512);
        uint4 A2 = *(const uint4*)(Ab + dst0 + 1024);
        uint4 A3 = *(const uint4*)(Ab + dst0 + 1536);
        mask4(A0, (uint32_t)-(int)(vsr & 1u));
        mask4(A1, (uint32_t)-(int)((vsr >> 1) & 1u));
        mask4(A2, (uint32_t)-(int)((vsr >> 2) & 1u));
        mask4(A3, (uint32_t)-(int)((vsr >> 3) & 1u));
        vsr >>= 4;

        // B fragments for this tap
        const uint4* wp = (const uint4*)(smem + (size_t)ctap * W_TAP);
        uint4 bf0 = wp[0 * 32 + lane];
        uint4 bf1 = wp[1 * 32 + lane];
        uint4 bf2 = wp[2 * 32 + lane];
        uint4 bf3 = wp[3 * 32 + lane];

        #pragma unroll
        for (int s = 0; s < 2; s++) {
            uint4 L = s ? A2 : A0;
            uint4 M = s ? A3 : A1;
            mma_f16(acc[s][0][0], acc[s][0][1], acc[s][0][2], acc[s][0][3],
                    L.x, M.x, L.y, M.y, bf0.x, bf0.y);
            mma_f16(acc[s][1][0], acc[s][1][1], acc[s][1][2], acc[s][1][3],
                    L.x, M.x, L.y, M.y, bf0.z, bf0.w);
            mma_f16(acc[s][2][0], acc[s][2][1], acc[s][2][2], acc[s][2][3],
                    L.x, M.x, L.y, M.y, bf1.x, bf1.y);
            mma_f16(acc[s][3][0], acc[s][3][1], acc[s][3][2], acc[s][3][3],
                    L.x, M.x, L.y, M.y, bf1.z, bf1.w);
            mma_f16(acc[s][0][0], acc[s][0][1], acc[s][0][2], acc[s][0][3],
                    L.z, M.z, L.w, M.w, bf2.x, bf2.y);
            mma_f16(acc[s][1][0], acc[s][1][1], acc[s][1][2], acc[s][1][3],
                    L.z, M.z, L.w, M.w, bf2.z, bf2.w);
            mma_f16(acc[s][2][0], acc[s][2][1], acc[s][2][2], acc[s][2][3],
                    L.z, M.z, L.w, M.w, bf3.x, bf3.y);
            mma_f16(acc[s][3][0], acc[s][3][1], acc[s][3][2], acc[s][3][3],
                    L.z, M.z, L.w, M.w, bf3.z, bf3.w);
        }

        if (++ctap == KVOL) {
            const float* bsm = (const float*)(smem + OFF_BIAS);
            #pragma unroll
            for (int s = 0; s < 2; s++) {
                int gr = cRow + s * 16 + gid;
                #pragma unroll
                for (int nt = 0; nt < 4; nt++) {
                    int col = nt * 8 + tig * 2;
                    float2 bv = *(const float2*)(bsm + col);
                    if (gr < N) {
                        float2 o = { acc[s][nt][0] + bv.x, acc[s][nt][1] + bv.y };
                        *(float2*)(out + (size_t)gr * COUT + col) = o;
                    }
                    if (gr + 8 < N) {
                        float2 o = { acc[s][nt][2] + bv.x, acc[s][nt][3] + bv.y };
                        *(float2*)(out + (size_t)(gr + 8) * COUT + col) = o;
                    }
                    acc[s][nt][0] = acc[s][nt][1] = acc[s][nt][2] = acc[s][nt][3] = 0.0f;
                }
            }
            ctap = 0;
            cRow += TW * ROWS_W;
        }
    }
}

extern "C" void kernel_launch(void* const* d_in, const int* in_sizes, int n_in,
                              void* d_out, int out_size) {
    const float*         feat   = (const float*)d_in[0];          // [N, 32]
    const float*         weight = (const float*)d_in[1];          // [27, 32, 32]
    const float*         bias   = (const float*)d_in[2];          // [32]
    const int*           kidx   = (const int*)d_in[3];            // [27, N]
    const unsigned char* kvalid = (const unsigned char*)d_in[4];  // [27, N] bool
    float* out = (float*)d_out;

    const int N = in_sizes[0] / CIN;

    int sms = 148;
    cudaDeviceGetAttribute(&sms, cudaDevAttrMultiProcessorCount, 0);

    cudaFuncSetAttribute(spconv_mma, cudaFuncAttributeMaxDynamicSharedMemorySize, SMEM_TOTAL);

    prepass<<<sms * 8, 256>>>(feat, kvalid, N);
    spconv_mma<<<sms, THREADS, SMEM_TOTAL>>>(weight, bias, kidx, kvalid, out, N);
}